// round 7
// baseline (speedup 1.0000x reference)
#include <cuda_runtime.h>
#include <cstdint>

// Problem constants (fixed shapes)
#define BB 4096
#define SS 2048
#define INW 8
#define HH 8

typedef unsigned long long u64;

__device__ int g_hist[SS];
__device__ int g_off[SS];
__device__ int g_perm[BB];

// ---------------- scalar helpers --------------
__device__ __forceinline__ float ex2f_(float x) {
    float r; asm("ex2.approx.f32 %0, %1;" : "=f"(r) : "f"(x)); return r;
}
__device__ __forceinline__ float rcpf_(float x) {
    float r; asm("rcp.approx.f32 %0, %1;" : "=f"(r) : "f"(x)); return r;
}
__device__ __forceinline__ float tanhf_(float x) {
    return fmaf(2.0f, rcpf_(1.0f + ex2f_(-2.8853900817779268f * x)), -1.0f);
}

// ---------------- packed f32x2 helpers (sm_103a) --------------
__device__ __forceinline__ u64 pk2(float lo, float hi) {
    u64 r; asm("mov.b64 %0, {%1, %2};" : "=l"(r) : "f"(lo), "f"(hi)); return r;
}
__device__ __forceinline__ void unpk2(u64 v, float& lo, float& hi) {
    asm("mov.b64 {%0, %1}, %2;" : "=f"(lo), "=f"(hi) : "l"(v));
}
__device__ __forceinline__ u64 ffma2(u64 a, u64 b, u64 c) {
    u64 d; asm("fma.rn.f32x2 %0, %1, %2, %3;" : "=l"(d) : "l"(a), "l"(b), "l"(c)); return d;
}
__device__ __forceinline__ float hsum2(u64 v) {
    float lo, hi; unpk2(v, lo, hi); return lo + hi;
}

// ---------------- counting sort by length, descending ----------------
__global__ void k_zero() {
    int i = blockIdx.x * blockDim.x + threadIdx.x;
    if (i < SS) g_hist[i] = 0;
}
__global__ void k_hist(const int* __restrict__ lengths) {
    int b = blockIdx.x * blockDim.x + threadIdx.x;
    if (b < BB) {
        int key = SS - lengths[b];
        atomicAdd(&g_hist[key], 1);
    }
}
__global__ void k_scan() {
    __shared__ int shA[SS];
    __shared__ int shB[SS];
    int t = threadIdx.x;
    shA[t] = g_hist[t];
    shA[t + 1024] = g_hist[t + 1024];
    __syncthreads();
    int* src = shA;
    int* dst = shB;
    for (int off = 1; off < SS; off <<= 1) {
        for (int i = t; i < SS; i += 1024) {
            int v = src[i];
            if (i >= off) v += src[i - off];
            dst[i] = v;
        }
        __syncthreads();
        int* tmp = src; src = dst; dst = tmp;
    }
    for (int i = t; i < SS; i += 1024) {
        g_off[i] = (i == 0) ? 0 : src[i - 1];
    }
}
__global__ void k_scatter(const int* __restrict__ lengths) {
    int b = blockIdx.x * blockDim.x + threadIdx.x;
    if (b < BB) {
        int key = SS - lengths[b];
        int p = atomicAdd(&g_off[key], 1);
        g_perm[p] = b;
    }
}

// ---------------- main LSTM kernel ----------------
// 8 lanes per sequence, 4 sequences per warp, 1024 warps (256 blocks x 128 thr).
// Lane m owns hidden unit m: computes ALL 4 gates (i,f,g,o), c_m and h_m locally
// for both layers -> no gate exchanges. Only the h vectors are rebroadcast,
// once per step, through a 32B smem slot + one __syncwarp.
// The two layers are software-pipelined: body(t) = { A(t+1) || B(t) }, two
// independent dependency chains that overlap under in-order issue.
__global__ __launch_bounds__(128)
void lstm_ac_kernel(const float* __restrict__ seq,
                    const int*   __restrict__ lengths,
                    const float* __restrict__ Wih0, const float* __restrict__ Whh0,
                    const float* __restrict__ bih0, const float* __restrict__ bhh0,
                    const float* __restrict__ Wih1, const float* __restrict__ Whh1,
                    const float* __restrict__ bih1, const float* __restrict__ bhh1,
                    const float* __restrict__ Wl,  const float* __restrict__ bl,
                    const float* __restrict__ Wv,  const float* __restrict__ bv,
                    const float* __restrict__ Wa,  const float* __restrict__ ba,
                    const float* __restrict__ log_std,
                    float* __restrict__ out)
{
    __shared__ __align__(16) float hbuf[4][4][2][8];  // [warp][grp][layer][m]
    __shared__ __align__(16) float ybuf[4][4][8];     // final h1 snapshot

    const unsigned FULL = 0xffffffffu;
    int lane = threadIdx.x & 31;
    int wib  = threadIdx.x >> 5;            // 0..3
    int grp  = lane >> 3;                   // 0..3 (sequence within warp)
    int m    = lane & 7;                    // hidden unit owned by this lane
    int g    = blockIdx.x + wib * 256;      // strided group assignment, 1024 groups

    int b   = g_perm[4 * g + grp];
    int len = lengths[b];
    int o1  = __shfl_xor_sync(FULL, len, 8);  int l2 = len > o1 ? len : o1;
    int o2  = __shfl_xor_sync(FULL, l2, 16);  int wmax = l2 > o2 ? l2 : o2;

    // activation prescale folded into weights/biases.
    // gate order: i (sigmoid), f (sigmoid), g (tanh), o (sigmoid)
    const float SG = -1.4426950408889634f;
    const float TH = -2.8853900817779268f;
    const float scl[4] = {SG, SG, TH, SG};

    u64 w0x[4][4], w0h[4][4], w1x[4][4], w1h[4][4], bs0[4], bs1[4];
#pragma unroll
    for (int gi = 0; gi < 4; gi++) {
        int r = m + 8 * gi;
        float s = scl[gi];
#pragma unroll
        for (int j = 0; j < 4; j++) {
            w0x[gi][j] = pk2(Wih0[r*8+2*j]*s, Wih0[r*8+2*j+1]*s);
            w0h[gi][j] = pk2(Whh0[r*8+2*j]*s, Whh0[r*8+2*j+1]*s);
            w1x[gi][j] = pk2(Wih1[r*8+2*j]*s, Wih1[r*8+2*j+1]*s);
            w1h[gi][j] = pk2(Whh1[r*8+2*j]*s, Whh1[r*8+2*j+1]*s);
        }
        bs0[gi] = pk2((bih0[r] + bhh0[r]) * s, 0.f);
        bs1[gi] = pk2((bih1[r] + bhh1[r]) * s, 0.f);
    }

    const ulonglong2* xrow = (const ulonglong2*)(seq + (size_t)b * SS * INW);

    // ---- prologue: A(0) with h0(-1)=0 ----
    float c0, c1 = 0.f;
    u64 h1r[4] = {0, 0, 0, 0};
    u64 h0r[4];
    {
        ulonglong2 xa = xrow[0], xb = xrow[1];
        u64 acc[4];
#pragma unroll
        for (int gi = 0; gi < 4; gi++) {
            u64 a = bs0[gi];
            a = ffma2(w0x[gi][0], xa.x, a);
            a = ffma2(w0x[gi][1], xa.y, a);
            a = ffma2(w0x[gi][2], xb.x, a);
            a = ffma2(w0x[gi][3], xb.y, a);
            acc[gi] = a;
        }
        float iv = rcpf_(1.0f + ex2f_(hsum2(acc[0])));
        float fv = rcpf_(1.0f + ex2f_(hsum2(acc[1])));
        float gv = fmaf(2.0f, rcpf_(1.0f + ex2f_(hsum2(acc[2]))), -1.0f);
        float ov = rcpf_(1.0f + ex2f_(hsum2(acc[3])));
        (void)fv;
        c0 = iv * gv;                       // f * 0 + i * g
        float h0m = ov * tanhf_(c0);
        hbuf[wib][grp][0][m] = h0m;
        __syncwarp();
        ulonglong2 q = *(const ulonglong2*)&hbuf[wib][grp][0][0];
        ulonglong2 p = *(const ulonglong2*)&hbuf[wib][grp][0][4];
        h0r[0] = q.x; h0r[1] = q.y; h0r[2] = p.x; h0r[3] = p.y;
    }

    // ---- main loop: body(t) = { B(t) || A(t+1) } ----
    for (int t = 0; t < wmax; t++) {
        // issue x(t+1) loads early (consumed ~100 instr later)
        int tn = (t + 1 < SS) ? (t + 1) : (SS - 1);
        ulonglong2 xa = xrow[2 * tn];
        ulonglong2 xb = xrow[2 * tn + 1];

        // B(t): layer1 gates from h0r(t), h1r(t-1)
        u64 bcc[4];
#pragma unroll
        for (int gi = 0; gi < 4; gi++) {
            u64 a = bs1[gi];
            a = ffma2(w1x[gi][0], h0r[0], a);
            a = ffma2(w1x[gi][1], h0r[1], a);
            a = ffma2(w1x[gi][2], h0r[2], a);
            a = ffma2(w1x[gi][3], h0r[3], a);
            a = ffma2(w1h[gi][0], h1r[0], a);
            a = ffma2(w1h[gi][1], h1r[1], a);
            a = ffma2(w1h[gi][2], h1r[2], a);
            a = ffma2(w1h[gi][3], h1r[3], a);
            bcc[gi] = a;
        }

        // A(t+1): layer0 gates from x(t+1), h0r(t)  (independent chain)
        u64 acc[4];
#pragma unroll
        for (int gi = 0; gi < 4; gi++) {
            u64 a = bs0[gi];
            a = ffma2(w0h[gi][0], h0r[0], a);
            a = ffma2(w0h[gi][1], h0r[1], a);
            a = ffma2(w0h[gi][2], h0r[2], a);
            a = ffma2(w0h[gi][3], h0r[3], a);
            a = ffma2(w0x[gi][0], xa.x, a);
            a = ffma2(w0x[gi][1], xa.y, a);
            a = ffma2(w0x[gi][2], xb.x, a);
            a = ffma2(w0x[gi][3], xb.y, a);
            acc[gi] = a;
        }

        // B activations + state update
        float bi = rcpf_(1.0f + ex2f_(hsum2(bcc[0])));
        float bf = rcpf_(1.0f + ex2f_(hsum2(bcc[1])));
        float bg = fmaf(2.0f, rcpf_(1.0f + ex2f_(hsum2(bcc[2]))), -1.0f);
        float bo = rcpf_(1.0f + ex2f_(hsum2(bcc[3])));
        c1 = fmaf(bf, c1, bi * bg);
        float h1m = bo * tanhf_(c1);

        // A activations + state update
        float ai = rcpf_(1.0f + ex2f_(hsum2(acc[0])));
        float af = rcpf_(1.0f + ex2f_(hsum2(acc[1])));
        float ag = fmaf(2.0f, rcpf_(1.0f + ex2f_(hsum2(acc[2]))), -1.0f);
        float ao = rcpf_(1.0f + ex2f_(hsum2(acc[3])));
        c0 = fmaf(af, c0, ai * ag);
        float h0m = ao * tanhf_(c0);

        // snapshot final h1 for this sequence (once)
        if (t == len - 1) ybuf[wib][grp][m] = h1m;

        // single combined exchange point
        hbuf[wib][grp][0][m] = h0m;
        hbuf[wib][grp][1][m] = h1m;
        __syncwarp();
        ulonglong2 q0 = *(const ulonglong2*)&hbuf[wib][grp][0][0];
        ulonglong2 q1 = *(const ulonglong2*)&hbuf[wib][grp][0][4];
        ulonglong2 r0 = *(const ulonglong2*)&hbuf[wib][grp][1][0];
        ulonglong2 r1 = *(const ulonglong2*)&hbuf[wib][grp][1][4];
        h0r[0] = q0.x; h0r[1] = q0.y; h0r[2] = q1.x; h0r[3] = q1.y;
        h1r[0] = r0.x; h1r[1] = r0.y; h1r[2] = r1.x; h1r[3] = r1.y;
    }

    __syncwarp();

    // ---- heads (lane m==0 of each group) ----
    if (m == 0) {
        float y[8];
#pragma unroll
        for (int k = 0; k < 8; k++) y[k] = ybuf[wib][grp][k];

        float feat[4];
#pragma unroll
        for (int j = 0; j < 4; j++) {
            float a = bl[j];
#pragma unroll
            for (int k = 0; k < 8; k++) a = fmaf(Wl[j * 8 + k], y[k], a);
            feat[j] = tanhf_(a);
        }
        float val = bv[0];
#pragma unroll
        for (int j = 0; j < 4; j++) val = fmaf(Wv[j], feat[j], val);
        out[b] = val;
#pragma unroll
        for (int a = 0; a < 4; a++) {
            float mv = ba[a];
#pragma unroll
            for (int j = 0; j < 4; j++) mv = fmaf(Wa[a * 4 + j], feat[j], mv);
            float ls = log_std[a];
            out[BB + b * 4 + a]          = mv;                               // action_mean
            out[BB + 4 * BB + b * 4 + a] = ls;                               // action_log_std
            out[BB + 8 * BB + b * 4 + a] = ex2f_(ls * 1.4426950408889634f);  // action_std
        }
    }
}

extern "C" void kernel_launch(void* const* d_in, const int* in_sizes, int n_in,
                              void* d_out, int out_size)
{
    const float* seq     = (const float*)d_in[0];
    const int*   lengths = (const int*)  d_in[1];
    const float* Wih0 = (const float*)d_in[2];
    const float* Whh0 = (const float*)d_in[3];
    const float* bih0 = (const float*)d_in[4];
    const float* bhh0 = (const float*)d_in[5];
    const float* Wih1 = (const float*)d_in[6];
    const float* Whh1 = (const float*)d_in[7];
    const float* bih1 = (const float*)d_in[8];
    const float* bhh1 = (const float*)d_in[9];
    const float* Wl   = (const float*)d_in[10];
    const float* bl   = (const float*)d_in[11];
    const float* Wv   = (const float*)d_in[12];
    const float* bv   = (const float*)d_in[13];
    const float* Wa   = (const float*)d_in[14];
    const float* ba   = (const float*)d_in[15];
    const float* log_std = (const float*)d_in[16];
    float* out = (float*)d_out;

    // length-descending counting sort -> g_perm
    k_zero<<<(SS + 1023) / 1024, 1024>>>();
    k_hist<<<(BB + 255) / 256, 256>>>(lengths);
    k_scan<<<1, 1024>>>();
    k_scatter<<<(BB + 255) / 256, 256>>>(lengths);

    // main: 1024 warps (4 seqs each, 8 lanes per seq), 256 blocks x 128 threads
    lstm_ac_kernel<<<256, 128>>>(seq, lengths,
                                 Wih0, Whh0, bih0, bhh0,
                                 Wih1, Whh1, bih1, bhh1,
                                 Wl, bl, Wv, bv, Wa, ba, log_std,
                                 out);
}

// round 8
// speedup vs baseline: 1.5187x; 1.5187x over previous
#include <cuda_runtime.h>
#include <cstdint>

// Problem constants (fixed shapes)
#define BB 4096
#define SS 2048
#define INW 8
#define HH 8

typedef unsigned long long u64;

__device__ int g_hist[SS];
__device__ int g_off[SS];
__device__ int g_perm[BB];

// ---------------- scalar helpers --------------
__device__ __forceinline__ float ex2f_(float x) {
    float r; asm("ex2.approx.f32 %0, %1;" : "=f"(r) : "f"(x)); return r;
}
__device__ __forceinline__ float rcpf_(float x) {
    float r; asm("rcp.approx.f32 %0, %1;" : "=f"(r) : "f"(x)); return r;
}
__device__ __forceinline__ float tanhf_(float x) {
    return fmaf(2.0f, rcpf_(1.0f + ex2f_(-2.8853900817779268f * x)), -1.0f);
}

// ---------------- packed f32x2 helpers (sm_103a) --------------
__device__ __forceinline__ u64 pk2(float lo, float hi) {
    u64 r; asm("mov.b64 %0, {%1, %2};" : "=l"(r) : "f"(lo), "f"(hi)); return r;
}
__device__ __forceinline__ void unpk2(u64 v, float& lo, float& hi) {
    asm("mov.b64 {%0, %1}, %2;" : "=f"(lo), "=f"(hi) : "l"(v));
}
__device__ __forceinline__ u64 ffma2(u64 a, u64 b, u64 c) {
    u64 d; asm("fma.rn.f32x2 %0, %1, %2, %3;" : "=l"(d) : "l"(a), "l"(b), "l"(c)); return d;
}
__device__ __forceinline__ u64 fadd2(u64 a, u64 b) {
    u64 d; asm("add.rn.f32x2 %0, %1, %2;" : "=l"(d) : "l"(a), "l"(b)); return d;
}
__device__ __forceinline__ float hsum2(u64 v) {
    float lo, hi; unpk2(v, lo, hi); return lo + hi;
}

// ---------------- cp.async helpers --------------
__device__ __forceinline__ void cpasync16(uint32_t saddr, const void* gaddr) {
    asm volatile("cp.async.cg.shared.global [%0], [%1], 16;\n" :: "r"(saddr), "l"(gaddr));
}
__device__ __forceinline__ void cpcommit() {
    asm volatile("cp.async.commit_group;\n" ::: "memory");
}
__device__ __forceinline__ void cpwait1() {
    asm volatile("cp.async.wait_group 1;\n" ::: "memory");
}
__device__ __forceinline__ void cpwaitall() {
    asm volatile("cp.async.wait_all;\n" ::: "memory");
}

// ---------------- counting sort by length, descending ----------------
__global__ void k_zero() {
    int i = blockIdx.x * blockDim.x + threadIdx.x;
    if (i < SS) g_hist[i] = 0;
}
__global__ void k_hist(const int* __restrict__ lengths) {
    int b = blockIdx.x * blockDim.x + threadIdx.x;
    if (b < BB) {
        int key = SS - lengths[b];
        atomicAdd(&g_hist[key], 1);
    }
}
__global__ void k_scan() {
    __shared__ int shA[SS];
    __shared__ int shB[SS];
    int t = threadIdx.x;
    shA[t] = g_hist[t];
    shA[t + 1024] = g_hist[t + 1024];
    __syncthreads();
    int* src = shA;
    int* dst = shB;
    for (int off = 1; off < SS; off <<= 1) {
        for (int i = t; i < SS; i += 1024) {
            int v = src[i];
            if (i >= off) v += src[i - off];
            dst[i] = v;
        }
        __syncthreads();
        int* tmp = src; src = dst; dst = tmp;
    }
    for (int i = t; i < SS; i += 1024) {
        g_off[i] = (i == 0) ? 0 : src[i - 1];
    }
}
__global__ void k_scatter(const int* __restrict__ lengths) {
    int b = blockIdx.x * blockDim.x + threadIdx.x;
    if (b < BB) {
        int key = SS - lengths[b];
        int p = atomicAdd(&g_off[key], 1);
        g_perm[p] = b;
    }
}

// ---------------- main LSTM kernel ----------------
// 8 lanes/seq, 4 seqs/warp, 1024 warps = 128 blocks x 256 threads (ONE wave).
// Lane m owns hidden unit m (all 4 gates + c_m + h_m locally, both layers).
// Layers software-pipelined: body(t) = { B(t) || A(t+1) }.
// x is staged GMEM -> SMEM via cp.async in 16-step chunks, double buffered,
// prefetched 2 chunks ahead: ZERO global loads in the recurrence loop.
// Chunk c stages x[(c*16+1) .. (c*16+16)] (A runs one step ahead of B).
__global__ __launch_bounds__(256)
void lstm_ac_kernel(const float* __restrict__ seq,
                    const int*   __restrict__ lengths,
                    const float* __restrict__ Wih0, const float* __restrict__ Whh0,
                    const float* __restrict__ bih0, const float* __restrict__ bhh0,
                    const float* __restrict__ Wih1, const float* __restrict__ Whh1,
                    const float* __restrict__ bih1, const float* __restrict__ bhh1,
                    const float* __restrict__ Wl,  const float* __restrict__ bl,
                    const float* __restrict__ Wv,  const float* __restrict__ bv,
                    const float* __restrict__ Wa,  const float* __restrict__ ba,
                    const float* __restrict__ log_std,
                    float* __restrict__ out)
{
    __shared__ __align__(16) float xstage[8][2][4][16][8]; // [warp][buf][grp][step][8] = 32 kB
    __shared__ __align__(16) float hbuf[8][4][2][8];       // [warp][grp][layer][m]

    const unsigned FULL = 0xffffffffu;
    int lane = threadIdx.x & 31;
    int wib  = threadIdx.x >> 5;            // 0..7
    int grp  = lane >> 3;                   // 0..3 (sequence within warp)
    int m    = lane & 7;                    // hidden unit owned by this lane
    int g    = blockIdx.x + wib * 128;      // strided group assignment, 1024 groups

    int b   = g_perm[4 * g + grp];
    int len = lengths[b];
    int o1  = __shfl_xor_sync(FULL, len, 8);  int l2 = len > o1 ? len : o1;
    int o2  = __shfl_xor_sync(FULL, l2, 16);  int wmax = l2 > o2 ? l2 : o2;

    // activation prescale folded into weights/biases.
    const float SG = -1.4426950408889634f;
    const float TH = -2.8853900817779268f;
    const float scl[4] = {SG, SG, TH, SG};

    u64 w0x[4][4], w0h[4][4], w1x[4][4], w1h[4][4], bs0[4], bs1[4];
#pragma unroll
    for (int gi = 0; gi < 4; gi++) {
        int r = m + 8 * gi;
        float s = scl[gi];
#pragma unroll
        for (int j = 0; j < 4; j++) {
            w0x[gi][j] = pk2(Wih0[r*8+2*j]*s, Wih0[r*8+2*j+1]*s);
            w0h[gi][j] = pk2(Whh0[r*8+2*j]*s, Whh0[r*8+2*j+1]*s);
            w1x[gi][j] = pk2(Wih1[r*8+2*j]*s, Wih1[r*8+2*j+1]*s);
            w1h[gi][j] = pk2(Whh1[r*8+2*j]*s, Whh1[r*8+2*j+1]*s);
        }
        bs0[gi] = pk2((bih0[r] + bhh0[r]) * s, 0.f);
        bs1[gi] = pk2((bih1[r] + bhh1[r]) * s, 0.f);
    }

    const float* xrow = seq + (size_t)b * SS * INW;

    // smem staging addresses (lane-fixed parts)
    uint32_t st_base = (uint32_t)__cvta_generic_to_shared(&xstage[wib][0][grp][0][0]);
    uint32_t st_lane = st_base + (uint32_t)m * 64u;     // lane writes steps 2m,2m+1
    const uint32_t BUFSTRIDE = 4u * 16u * 8u * 4u;      // bytes between buf 0 and buf 1

    // prefetch chunk cc into buf cc&1 : stages x[(cc*16+1) .. (cc*16+16)]
    auto prefetch = [&](int cc) {
        int Tg = cc * 16 + 1 + 2 * m;                   // first step this lane loads
        if (Tg > SS - 2) Tg = SS - 2;                   // clamp (garbage only feeds discarded A)
        const float* gsrc = xrow + (size_t)Tg * 8;
        uint32_t sdst = st_lane + (uint32_t)(cc & 1) * BUFSTRIDE;
        cpasync16(sdst,      gsrc);
        cpasync16(sdst + 16, gsrc + 4);
        cpasync16(sdst + 32, gsrc + 8);
        cpasync16(sdst + 48, gsrc + 12);
        cpcommit();
    };

    // ---- prologue: A(0) with h0(-1)=0 (direct LDG, one time) ----
    float c0, c1 = 0.f;
    u64 h1r[4] = {0, 0, 0, 0};
    u64 h0r[4];
    u64 yp[4]  = {0, 0, 0, 0};
    {
        ulonglong2 xa = ((const ulonglong2*)xrow)[0];
        ulonglong2 xb = ((const ulonglong2*)xrow)[1];
        u64 acc[4];
#pragma unroll
        for (int gi = 0; gi < 4; gi++) {
            u64 a = ffma2(w0x[gi][0], xa.x, bs0[gi]);
            a = ffma2(w0x[gi][1], xa.y, a);
            a = ffma2(w0x[gi][2], xb.x, a);
            a = ffma2(w0x[gi][3], xb.y, a);
            acc[gi] = a;
        }
        float iv = rcpf_(1.0f + ex2f_(hsum2(acc[0])));
        float gv = fmaf(2.0f, rcpf_(1.0f + ex2f_(hsum2(acc[2]))), -1.0f);
        float ov = rcpf_(1.0f + ex2f_(hsum2(acc[3])));
        c0 = iv * gv;
        float h0m = ov * tanhf_(c0);
        hbuf[wib][grp][0][m] = h0m;
        __syncwarp();
        ulonglong2 q = *(const ulonglong2*)&hbuf[wib][grp][0][0];
        ulonglong2 p = *(const ulonglong2*)&hbuf[wib][grp][0][4];
        h0r[0] = q.x; h0r[1] = q.y; h0r[2] = p.x; h0r[3] = p.y;
    }

    int chunks = (wmax + 15) >> 4;
    prefetch(0);
    prefetch(1);

    // ---- main loop over chunks of 16 steps ----
    for (int c = 0; c < chunks; c++) {
        cpwait1();            // chunk c landed (c+1 may still be in flight)
        __syncwarp();
        const float* xbuf = &xstage[wib][c & 1][grp][0][0];

        for (int i = 0; i < 16; i++) {
            int t = (c << 4) + i;
            if (t >= wmax) break;                         // warp-uniform

            // x(t+1) from staged smem (slot i), broadcast LDS
            const ulonglong2* xs = (const ulonglong2*)(xbuf + i * 8);
            ulonglong2 xa = xs[0], xb = xs[1];

            // ---- B(t): layer1 gates from h0r(t), h1r(t-1) ----
            u64 bcc[4];
#pragma unroll
            for (int gi = 0; gi < 4; gi++) {
                u64 p = ffma2(w1x[gi][0], h0r[0], bs1[gi]);
                p = ffma2(w1x[gi][1], h0r[1], p);
                p = ffma2(w1x[gi][2], h0r[2], p);
                p = ffma2(w1x[gi][3], h0r[3], p);
                u64 q = ffma2(w1h[gi][0], h1r[0], (u64)0);
                q = ffma2(w1h[gi][1], h1r[1], q);
                q = ffma2(w1h[gi][2], h1r[2], q);
                q = ffma2(w1h[gi][3], h1r[3], q);
                bcc[gi] = fadd2(p, q);
            }

            // ---- A(t+1): layer0 gates from x(t+1), h0r(t) ----
            u64 acc[4];
#pragma unroll
            for (int gi = 0; gi < 4; gi++) {
                u64 p = ffma2(w0h[gi][0], h0r[0], bs0[gi]);
                p = ffma2(w0h[gi][1], h0r[1], p);
                p = ffma2(w0h[gi][2], h0r[2], p);
                p = ffma2(w0h[gi][3], h0r[3], p);
                u64 q = ffma2(w0x[gi][0], xa.x, (u64)0);
                q = ffma2(w0x[gi][1], xa.y, q);
                q = ffma2(w0x[gi][2], xb.x, q);
                q = ffma2(w0x[gi][3], xb.y, q);
                acc[gi] = fadd2(p, q);
            }

            // B activations + state update
            float bi = rcpf_(1.0f + ex2f_(hsum2(bcc[0])));
            float bf = rcpf_(1.0f + ex2f_(hsum2(bcc[1])));
            float bg = fmaf(2.0f, rcpf_(1.0f + ex2f_(hsum2(bcc[2]))), -1.0f);
            float bo = rcpf_(1.0f + ex2f_(hsum2(bcc[3])));
            c1 = fmaf(bf, c1, bi * bg);
            float h1m = bo * tanhf_(c1);

            // A activations + state update
            float ai = rcpf_(1.0f + ex2f_(hsum2(acc[0])));
            float af = rcpf_(1.0f + ex2f_(hsum2(acc[1])));
            float ag = fmaf(2.0f, rcpf_(1.0f + ex2f_(hsum2(acc[2]))), -1.0f);
            float ao = rcpf_(1.0f + ex2f_(hsum2(acc[3])));
            c0 = fmaf(af, c0, ai * ag);
            float h0m = ao * tanhf_(c0);

            // single combined exchange point
            hbuf[wib][grp][0][m] = h0m;
            hbuf[wib][grp][1][m] = h1m;
            __syncwarp();
            ulonglong2 q0 = *(const ulonglong2*)&hbuf[wib][grp][0][0];
            ulonglong2 q1 = *(const ulonglong2*)&hbuf[wib][grp][0][4];
            ulonglong2 r0 = *(const ulonglong2*)&hbuf[wib][grp][1][0];
            ulonglong2 r1 = *(const ulonglong2*)&hbuf[wib][grp][1][4];
            h0r[0] = q0.x; h0r[1] = q0.y; h0r[2] = q1.x; h0r[3] = q1.y;
            h1r[0] = r0.x; h1r[1] = r0.y; h1r[2] = r1.x; h1r[3] = r1.y;

            // snapshot final h1 (h1r now holds h1(t); register-replicated)
            if (t == len - 1) { yp[0] = h1r[0]; yp[1] = h1r[1]; yp[2] = h1r[2]; yp[3] = h1r[3]; }
        }

        prefetch(c + 2);     // all reads of buf (c&1) done -> safe to refill
    }

    cpwaitall();
    __syncwarp();

    // ---- heads (lane m==0 of each group holds full y in yp) ----
    if (m == 0) {
        float y[8];
        unpk2(yp[0], y[0], y[1]);
        unpk2(yp[1], y[2], y[3]);
        unpk2(yp[2], y[4], y[5]);
        unpk2(yp[3], y[6], y[7]);

        float feat[4];
#pragma unroll
        for (int j = 0; j < 4; j++) {
            float a = bl[j];
#pragma unroll
            for (int k = 0; k < 8; k++) a = fmaf(Wl[j * 8 + k], y[k], a);
            feat[j] = tanhf_(a);
        }
        float val = bv[0];
#pragma unroll
        for (int j = 0; j < 4; j++) val = fmaf(Wv[j], feat[j], val);
        out[b] = val;
#pragma unroll
        for (int a = 0; a < 4; a++) {
            float mv = ba[a];
#pragma unroll
            for (int j = 0; j < 4; j++) mv = fmaf(Wa[a * 4 + j], feat[j], mv);
            float ls = log_std[a];
            out[BB + b * 4 + a]          = mv;                               // action_mean
            out[BB + 4 * BB + b * 4 + a] = ls;                               // action_log_std
            out[BB + 8 * BB + b * 4 + a] = ex2f_(ls * 1.4426950408889634f);  // action_std
        }
    }
}

extern "C" void kernel_launch(void* const* d_in, const int* in_sizes, int n_in,
                              void* d_out, int out_size)
{
    const float* seq     = (const float*)d_in[0];
    const int*   lengths = (const int*)  d_in[1];
    const float* Wih0 = (const float*)d_in[2];
    const float* Whh0 = (const float*)d_in[3];
    const float* bih0 = (const float*)d_in[4];
    const float* bhh0 = (const float*)d_in[5];
    const float* Wih1 = (const float*)d_in[6];
    const float* Whh1 = (const float*)d_in[7];
    const float* bih1 = (const float*)d_in[8];
    const float* bhh1 = (const float*)d_in[9];
    const float* Wl   = (const float*)d_in[10];
    const float* bl   = (const float*)d_in[11];
    const float* Wv   = (const float*)d_in[12];
    const float* bv   = (const float*)d_in[13];
    const float* Wa   = (const float*)d_in[14];
    const float* ba   = (const float*)d_in[15];
    const float* log_std = (const float*)d_in[16];
    float* out = (float*)d_out;

    // length-descending counting sort -> g_perm
    k_zero<<<(SS + 1023) / 1024, 1024>>>();
    k_hist<<<(BB + 255) / 256, 256>>>(lengths);
    k_scan<<<1, 1024>>>();
    k_scatter<<<(BB + 255) / 256, 256>>>(lengths);

    // main: 1024 warps (4 seqs each, 8 lanes/seq), 128 blocks x 256 threads = ONE wave
    lstm_ac_kernel<<<128, 256>>>(seq, lengths,
                                 Wih0, Whh0, bih0, bhh0,
                                 Wih1, Whh1, bih1, bhh1,
                                 Wl, bl, Wv, bv, Wa, ba, log_std,
                                 out);
}

// round 9
// speedup vs baseline: 1.8764x; 1.2355x over previous
#include <cuda_runtime.h>
#include <cstdint>

// Problem constants (fixed shapes)
#define BB 4096
#define SS 2048
#define INW 8
#define HH 8

typedef unsigned long long u64;

__device__ int g_hist[SS];
__device__ int g_off[SS];
__device__ int g_perm[BB];

// ---------------- scalar helpers --------------
__device__ __forceinline__ float ex2f_(float x) {
    float r; asm("ex2.approx.f32 %0, %1;" : "=f"(r) : "f"(x)); return r;
}
__device__ __forceinline__ float rcpf_(float x) {
    float r; asm("rcp.approx.f32 %0, %1;" : "=f"(r) : "f"(x)); return r;
}
__device__ __forceinline__ float tanhf_(float x) {
    return fmaf(2.0f, rcpf_(1.0f + ex2f_(-2.8853900817779268f * x)), -1.0f);
}

// ---------------- packed f32x2 helpers (sm_103a) --------------
__device__ __forceinline__ u64 pk2(float lo, float hi) {
    u64 r; asm("mov.b64 %0, {%1, %2};" : "=l"(r) : "f"(lo), "f"(hi)); return r;
}
__device__ __forceinline__ void unpk2(u64 v, float& lo, float& hi) {
    asm("mov.b64 {%0, %1}, %2;" : "=f"(lo), "=f"(hi) : "l"(v));
}
__device__ __forceinline__ u64 ffma2(u64 a, u64 b, u64 c) {
    u64 d; asm("fma.rn.f32x2 %0, %1, %2, %3;" : "=l"(d) : "l"(a), "l"(b), "l"(c)); return d;
}
__device__ __forceinline__ u64 fadd2(u64 a, u64 b) {
    u64 d; asm("add.rn.f32x2 %0, %1, %2;" : "=l"(d) : "l"(a), "l"(b)); return d;
}
__device__ __forceinline__ float hsum2(u64 v) {
    float lo, hi; unpk2(v, lo, hi); return lo + hi;
}

// ---------------- cp.async helpers --------------
__device__ __forceinline__ void cpasync16(uint32_t saddr, const void* gaddr) {
    asm volatile("cp.async.cg.shared.global [%0], [%1], 16;\n" :: "r"(saddr), "l"(gaddr));
}
__device__ __forceinline__ void cpcommit() {
    asm volatile("cp.async.commit_group;\n" ::: "memory");
}
__device__ __forceinline__ void cpwait1() {
    asm volatile("cp.async.wait_group 1;\n" ::: "memory");
}
__device__ __forceinline__ void cpwaitall() {
    asm volatile("cp.async.wait_all;\n" ::: "memory");
}

// ---------------- counting sort by length, descending ----------------
__global__ void k_zero() {
    int i = blockIdx.x * blockDim.x + threadIdx.x;
    if (i < SS) g_hist[i] = 0;
}
__global__ void k_hist(const int* __restrict__ lengths) {
    int b = blockIdx.x * blockDim.x + threadIdx.x;
    if (b < BB) {
        int key = SS - lengths[b];
        atomicAdd(&g_hist[key], 1);
    }
}
__global__ void k_scan() {
    __shared__ int shA[SS];
    __shared__ int shB[SS];
    int t = threadIdx.x;
    shA[t] = g_hist[t];
    shA[t + 1024] = g_hist[t + 1024];
    __syncthreads();
    int* src = shA;
    int* dst = shB;
    for (int off = 1; off < SS; off <<= 1) {
        for (int i = t; i < SS; i += 1024) {
            int v = src[i];
            if (i >= off) v += src[i - off];
            dst[i] = v;
        }
        __syncthreads();
        int* tmp = src; src = dst; dst = tmp;
    }
    for (int i = t; i < SS; i += 1024) {
        g_off[i] = (i == 0) ? 0 : src[i - 1];
    }
}
__global__ void k_scatter(const int* __restrict__ lengths) {
    int b = blockIdx.x * blockDim.x + threadIdx.x;
    if (b < BB) {
        int key = SS - lengths[b];
        int p = atomicAdd(&g_off[key], 1);
        g_perm[p] = b;
    }
}

// ---------------- main LSTM kernel ----------------
// 8 lanes/seq, 4 seqs/warp, 1024 warps = 128 blocks x 256 threads (ONE wave).
// Lane m owns hidden unit m (all 4 gates + c_m + h_m locally, both layers).
// Layers software-pipelined: body(t) = { B(t) || A(t+1) }.
// x staged GMEM->SMEM via cp.async (16-step chunks, double buffer, 2 ahead).
// SMSP anti-correlated pairing: warp k<4 -> g=b+128k (longer), warp k+4 ->
// g=1023-(b+128k) (shorter); each SMSP's two warps sum to ~constant steps.
// Reciprocal batching: one rcp per gate-quad / tanh-pair instead of one each.
__global__ __launch_bounds__(256)
void lstm_ac_kernel(const float* __restrict__ seq,
                    const int*   __restrict__ lengths,
                    const float* __restrict__ Wih0, const float* __restrict__ Whh0,
                    const float* __restrict__ bih0, const float* __restrict__ bhh0,
                    const float* __restrict__ Wih1, const float* __restrict__ Whh1,
                    const float* __restrict__ bih1, const float* __restrict__ bhh1,
                    const float* __restrict__ Wl,  const float* __restrict__ bl,
                    const float* __restrict__ Wv,  const float* __restrict__ bv,
                    const float* __restrict__ Wa,  const float* __restrict__ ba,
                    const float* __restrict__ log_std,
                    float* __restrict__ out)
{
    __shared__ __align__(16) float xstage[8][2][4][16][8]; // [warp][buf][grp][step][8] = 32 kB
    __shared__ __align__(16) float hbuf[8][4][2][8];       // [warp][grp][layer][m]

    const unsigned FULL = 0xffffffffu;
    int lane = threadIdx.x & 31;
    int wib  = threadIdx.x >> 5;            // 0..7
    int grp  = lane >> 3;                   // 0..3 (sequence within warp)
    int m    = lane & 7;                    // hidden unit owned by this lane

    // anti-correlated SMSP pairing (warps {k, k+4} share an SMSP)
    int gl = blockIdx.x + 128 * (wib & 3);
    int g  = (wib < 4) ? gl : (1023 - gl);

    int b   = g_perm[4 * g + grp];
    int len = lengths[b];
    int o1  = __shfl_xor_sync(FULL, len, 8);  int l2 = len > o1 ? len : o1;
    int o2  = __shfl_xor_sync(FULL, l2, 16);  int wmax = l2 > o2 ? l2 : o2;

    // activation prescale folded into weights/biases.
    const float SG = -1.4426950408889634f;
    const float TH = -2.8853900817779268f;
    const float scl[4] = {SG, SG, TH, SG};

    u64 w0x[4][4], w0h[4][4], w1x[4][4], w1h[4][4], bs0[4], bs1[4];
#pragma unroll
    for (int gi = 0; gi < 4; gi++) {
        int r = m + 8 * gi;
        float s = scl[gi];
#pragma unroll
        for (int j = 0; j < 4; j++) {
            w0x[gi][j] = pk2(Wih0[r*8+2*j]*s, Wih0[r*8+2*j+1]*s);
            w0h[gi][j] = pk2(Whh0[r*8+2*j]*s, Whh0[r*8+2*j+1]*s);
            w1x[gi][j] = pk2(Wih1[r*8+2*j]*s, Wih1[r*8+2*j+1]*s);
            w1h[gi][j] = pk2(Whh1[r*8+2*j]*s, Whh1[r*8+2*j+1]*s);
        }
        bs0[gi] = pk2((bih0[r] + bhh0[r]) * s, 0.f);
        bs1[gi] = pk2((bih1[r] + bhh1[r]) * s, 0.f);
    }

    const float* xrow = seq + (size_t)b * SS * INW;

    uint32_t st_base = (uint32_t)__cvta_generic_to_shared(&xstage[wib][0][grp][0][0]);
    uint32_t st_lane = st_base + (uint32_t)m * 64u;
    const uint32_t BUFSTRIDE = 4u * 16u * 8u * 4u;

    auto prefetch = [&](int cc) {
        int Tg = cc * 16 + 1 + 2 * m;
        if (Tg > SS - 2) Tg = SS - 2;
        const float* gsrc = xrow + (size_t)Tg * 8;
        uint32_t sdst = st_lane + (uint32_t)(cc & 1) * BUFSTRIDE;
        cpasync16(sdst,      gsrc);
        cpasync16(sdst + 16, gsrc + 4);
        cpasync16(sdst + 32, gsrc + 8);
        cpasync16(sdst + 48, gsrc + 12);
        cpcommit();
    };

    // ---- prologue: A(0) with h0(-1)=0 ----
    float c0, c1 = 0.f;
    u64 h1r[4] = {0, 0, 0, 0};
    u64 h0r[4];
    u64 yp[4]  = {0, 0, 0, 0};
    {
        ulonglong2 xa = ((const ulonglong2*)xrow)[0];
        ulonglong2 xb = ((const ulonglong2*)xrow)[1];
        u64 acc[4];
#pragma unroll
        for (int gi = 0; gi < 4; gi++) {
            u64 a = ffma2(w0x[gi][0], xa.x, bs0[gi]);
            a = ffma2(w0x[gi][1], xa.y, a);
            a = ffma2(w0x[gi][2], xb.x, a);
            a = ffma2(w0x[gi][3], xb.y, a);
            acc[gi] = a;
        }
        float iv = rcpf_(1.0f + ex2f_(hsum2(acc[0])));
        float gv = fmaf(2.0f, rcpf_(1.0f + ex2f_(hsum2(acc[2]))), -1.0f);
        float ov = rcpf_(1.0f + ex2f_(hsum2(acc[3])));
        c0 = iv * gv;
        float h0m = ov * tanhf_(c0);
        hbuf[wib][grp][0][m] = h0m;
        __syncwarp();
        ulonglong2 q = *(const ulonglong2*)&hbuf[wib][grp][0][0];
        ulonglong2 p = *(const ulonglong2*)&hbuf[wib][grp][0][4];
        h0r[0] = q.x; h0r[1] = q.y; h0r[2] = p.x; h0r[3] = p.y;
    }

    int chunks = (wmax + 15) >> 4;
    prefetch(0);
    prefetch(1);

    // ---- main loop over chunks of 16 steps ----
    for (int c = 0; c < chunks; c++) {
        cpwait1();
        __syncwarp();
        const float* xbuf = &xstage[wib][c & 1][grp][0][0];

        for (int i = 0; i < 16; i++) {
            int t = (c << 4) + i;
            if (t >= wmax) break;                         // warp-uniform

            const ulonglong2* xs = (const ulonglong2*)(xbuf + i * 8);
            ulonglong2 xa = xs[0], xb = xs[1];

            // ---- B(t): layer1 gates from h0r(t), h1r(t-1) ----
            u64 bcc[4];
#pragma unroll
            for (int gi = 0; gi < 4; gi++) {
                u64 p = ffma2(w1x[gi][0], h0r[0], bs1[gi]);
                p = ffma2(w1x[gi][1], h0r[1], p);
                p = ffma2(w1x[gi][2], h0r[2], p);
                p = ffma2(w1x[gi][3], h0r[3], p);
                u64 q = ffma2(w1h[gi][0], h1r[0], (u64)0);
                q = ffma2(w1h[gi][1], h1r[1], q);
                q = ffma2(w1h[gi][2], h1r[2], q);
                q = ffma2(w1h[gi][3], h1r[3], q);
                bcc[gi] = fadd2(p, q);
            }

            // ---- A(t+1): layer0 gates from x(t+1), h0r(t) ----
            u64 acc[4];
#pragma unroll
            for (int gi = 0; gi < 4; gi++) {
                u64 p = ffma2(w0h[gi][0], h0r[0], bs0[gi]);
                p = ffma2(w0h[gi][1], h0r[1], p);
                p = ffma2(w0h[gi][2], h0r[2], p);
                p = ffma2(w0h[gi][3], h0r[3], p);
                u64 q = ffma2(w0x[gi][0], xa.x, (u64)0);
                q = ffma2(w0x[gi][1], xa.y, q);
                q = ffma2(w0x[gi][2], xb.x, q);
                q = ffma2(w0x[gi][3], xb.y, q);
                acc[gi] = fadd2(p, q);
            }

            // ---- B activations: batched reciprocal over the 4-gate quad ----
            float bd0 = 1.0f + ex2f_(hsum2(bcc[0]));   // i
            float bd1 = 1.0f + ex2f_(hsum2(bcc[1]));   // f
            float bd2 = 1.0f + ex2f_(hsum2(bcc[2]));   // g (tanh form)
            float bd3 = 1.0f + ex2f_(hsum2(bcc[3]));   // o
            float bp01 = bd0 * bd1, bp23 = bd2 * bd3;
            float bR   = rcpf_(bp01 * bp23);
            float br01 = bR * bp23, br23 = bR * bp01;
            float bi = br01 * bd1;
            float bf = br01 * bd0;
            float bg = fmaf(2.0f, br23 * bd3, -1.0f);
            float bo = br23 * bd2;
            c1 = fmaf(bf, c1, bi * bg);

            // ---- A activations: batched reciprocal ----
            float ad0 = 1.0f + ex2f_(hsum2(acc[0]));
            float ad1 = 1.0f + ex2f_(hsum2(acc[1]));
            float ad2 = 1.0f + ex2f_(hsum2(acc[2]));
            float ad3 = 1.0f + ex2f_(hsum2(acc[3]));
            float ap01 = ad0 * ad1, ap23 = ad2 * ad3;
            float aR   = rcpf_(ap01 * ap23);
            float ar01 = aR * ap23, ar23 = aR * ap01;
            float ai = ar01 * ad1;
            float af = ar01 * ad0;
            float ag = fmaf(2.0f, ar23 * ad3, -1.0f);
            float ao = ar23 * ad2;
            c0 = fmaf(af, c0, ai * ag);

            // ---- paired tanh(c0), tanh(c1): one rcp for both ----
            float td1 = 1.0f + ex2f_(c1 * TH);
            float td0 = 1.0f + ex2f_(c0 * TH);
            float tR  = rcpf_(td0 * td1);
            float h1m = bo * fmaf(2.0f, tR * td0, -1.0f);
            float h0m = ao * fmaf(2.0f, tR * td1, -1.0f);

            // single combined exchange point
            hbuf[wib][grp][0][m] = h0m;
            hbuf[wib][grp][1][m] = h1m;
            __syncwarp();
            ulonglong2 q0 = *(const ulonglong2*)&hbuf[wib][grp][0][0];
            ulonglong2 q1 = *(const ulonglong2*)&hbuf[wib][grp][0][4];
            ulonglong2 r0 = *(const ulonglong2*)&hbuf[wib][grp][1][0];
            ulonglong2 r1 = *(const ulonglong2*)&hbuf[wib][grp][1][4];
            h0r[0] = q0.x; h0r[1] = q0.y; h0r[2] = q1.x; h0r[3] = q1.y;
            h1r[0] = r0.x; h1r[1] = r0.y; h1r[2] = r1.x; h1r[3] = r1.y;

            if (t == len - 1) { yp[0] = h1r[0]; yp[1] = h1r[1]; yp[2] = h1r[2]; yp[3] = h1r[3]; }
        }

        prefetch(c + 2);
    }

    cpwaitall();
    __syncwarp();

    // ---- heads (lane m==0 of each group holds full y in yp) ----
    if (m == 0) {
        float y[8];
        unpk2(yp[0], y[0], y[1]);
        unpk2(yp[1], y[2], y[3]);
        unpk2(yp[2], y[4], y[5]);
        unpk2(yp[3], y[6], y[7]);

        float feat[4];
#pragma unroll
        for (int j = 0; j < 4; j++) {
            float a = bl[j];
#pragma unroll
            for (int k = 0; k < 8; k++) a = fmaf(Wl[j * 8 + k], y[k], a);
            feat[j] = tanhf_(a);
        }
        float val = bv[0];
#pragma unroll
        for (int j = 0; j < 4; j++) val = fmaf(Wv[j], feat[j], val);
        out[b] = val;
#pragma unroll
        for (int a = 0; a < 4; a++) {
            float mv = ba[a];
#pragma unroll
            for (int j = 0; j < 4; j++) mv = fmaf(Wa[a * 4 + j], feat[j], mv);
            float ls = log_std[a];
            out[BB + b * 4 + a]          = mv;                               // action_mean
            out[BB + 4 * BB + b * 4 + a] = ls;                               // action_log_std
            out[BB + 8 * BB + b * 4 + a] = ex2f_(ls * 1.4426950408889634f);  // action_std
        }
    }
}

extern "C" void kernel_launch(void* const* d_in, const int* in_sizes, int n_in,
                              void* d_out, int out_size)
{
    const float* seq     = (const float*)d_in[0];
    const int*   lengths = (const int*)  d_in[1];
    const float* Wih0 = (const float*)d_in[2];
    const float* Whh0 = (const float*)d_in[3];
    const float* bih0 = (const float*)d_in[4];
    const float* bhh0 = (const float*)d_in[5];
    const float* Wih1 = (const float*)d_in[6];
    const float* Whh1 = (const float*)d_in[7];
    const float* bih1 = (const float*)d_in[8];
    const float* bhh1 = (const float*)d_in[9];
    const float* Wl   = (const float*)d_in[10];
    const float* bl   = (const float*)d_in[11];
    const float* Wv   = (const float*)d_in[12];
    const float* bv   = (const float*)d_in[13];
    const float* Wa   = (const float*)d_in[14];
    const float* ba   = (const float*)d_in[15];
    const float* log_std = (const float*)d_in[16];
    float* out = (float*)d_out;

    // length-descending counting sort -> g_perm
    k_zero<<<(SS + 1023) / 1024, 1024>>>();
    k_hist<<<(BB + 255) / 256, 256>>>(lengths);
    k_scan<<<1, 1024>>>();
    k_scatter<<<(BB + 255) / 256, 256>>>(lengths);

    // main: 1024 warps (4 seqs each, 8 lanes/seq), 128 blocks x 256 threads = ONE wave
    lstm_ac_kernel<<<128, 256>>>(seq, lengths,
                                 Wih0, Whh0, bih0, bhh0,
                                 Wih1, Whh1, bih1, bhh1,
                                 Wl, bl, Wv, bv, Wa, ba, log_std,
                                 out);
}

// round 11
// speedup vs baseline: 1.9402x; 1.0340x over previous
#include <cuda_runtime.h>
#include <cstdint>

// Problem constants (fixed shapes)
#define BB 4096
#define SS 2048
#define INW 8
#define HH 8

typedef unsigned long long u64;

__device__ int g_hist[SS];
__device__ int g_off[SS];
__device__ int g_perm[BB];

// ---------------- scalar helpers --------------
__device__ __forceinline__ float ex2f_(float x) {
    float r; asm("ex2.approx.f32 %0, %1;" : "=f"(r) : "f"(x)); return r;
}
__device__ __forceinline__ float rcpf_(float x) {
    float r; asm("rcp.approx.f32 %0, %1;" : "=f"(r) : "f"(x)); return r;
}
__device__ __forceinline__ float tanhf_(float x) {
    return fmaf(2.0f, rcpf_(1.0f + ex2f_(-2.8853900817779268f * x)), -1.0f);
}

// ---------------- packed f32x2 helpers (sm_103a) --------------
__device__ __forceinline__ u64 pk2(float lo, float hi) {
    u64 r; asm("mov.b64 %0, {%1, %2};" : "=l"(r) : "f"(lo), "f"(hi)); return r;
}
__device__ __forceinline__ void unpk2(u64 v, float& lo, float& hi) {
    asm("mov.b64 {%0, %1}, %2;" : "=f"(lo), "=f"(hi) : "l"(v));
}
__device__ __forceinline__ u64 ffma2(u64 a, u64 b, u64 c) {
    u64 d; asm("fma.rn.f32x2 %0, %1, %2, %3;" : "=l"(d) : "l"(a), "l"(b), "l"(c)); return d;
}
__device__ __forceinline__ u64 fadd2(u64 a, u64 b) {
    u64 d; asm("add.rn.f32x2 %0, %1, %2;" : "=l"(d) : "l"(a), "l"(b)); return d;
}
__device__ __forceinline__ u64 fmul2(u64 a, u64 b) {
    u64 d; asm("mul.rn.f32x2 %0, %1, %2;" : "=l"(d) : "l"(a), "l"(b)); return d;
}
__device__ __forceinline__ float hsum2(u64 v) {
    float lo, hi; unpk2(v, lo, hi); return lo + hi;
}

// ---------------- cp.async helpers --------------
__device__ __forceinline__ void cpasync16(uint32_t saddr, const void* gaddr) {
    asm volatile("cp.async.cg.shared.global [%0], [%1], 16;\n" :: "r"(saddr), "l"(gaddr));
}
__device__ __forceinline__ void cpcommit() {
    asm volatile("cp.async.commit_group;\n" ::: "memory");
}
__device__ __forceinline__ void cpwait1() {
    asm volatile("cp.async.wait_group 1;\n" ::: "memory");
}
__device__ __forceinline__ void cpwaitall() {
    asm volatile("cp.async.wait_all;\n" ::: "memory");
}

// ---------------- counting sort by length, descending ----------------
__global__ void k_zero() {
    int i = blockIdx.x * blockDim.x + threadIdx.x;
    if (i < SS) g_hist[i] = 0;
}
__global__ void k_hist(const int* __restrict__ lengths) {
    int b = blockIdx.x * blockDim.x + threadIdx.x;
    if (b < BB) {
        int key = SS - lengths[b];
        atomicAdd(&g_hist[key], 1);
    }
}
__global__ void k_scan() {
    __shared__ int shA[SS];
    __shared__ int shB[SS];
    int t = threadIdx.x;
    shA[t] = g_hist[t];
    shA[t + 1024] = g_hist[t + 1024];
    __syncthreads();
    int* src = shA;
    int* dst = shB;
    for (int off = 1; off < SS; off <<= 1) {
        for (int i = t; i < SS; i += 1024) {
            int v = src[i];
            if (i >= off) v += src[i - off];
            dst[i] = v;
        }
        __syncthreads();
        int* tmp = src; src = dst; dst = tmp;
    }
    for (int i = t; i < SS; i += 1024) {
        g_off[i] = (i == 0) ? 0 : src[i - 1];
    }
}
__global__ void k_scatter(const int* __restrict__ lengths) {
    int b = blockIdx.x * blockDim.x + threadIdx.x;
    if (b < BB) {
        int key = SS - lengths[b];
        int p = atomicAdd(&g_off[key], 1);
        g_perm[p] = b;
    }
}

// ---------------- main LSTM kernel ----------------
// 8 lanes/seq, 4 seqs/warp, 1024 warps = 128 blocks x 256 threads (ONE wave).
// Lane m owns hidden unit m (all 4 gates + c_m + h_m locally, both layers).
// Layers software-pipelined: body(t) = { B(t) || A(t+1) }.
// x staged GMEM->SMEM via cp.async (16-step chunks, double buffer, 2 ahead).
// Anti-correlated SMSP pairing (warps {k,k+4} share an SMSP, lengths sum ~const).
// Epilogue fully packed f32x2 across the layer pair (lo = layer1/B, hi = layer0/A):
// one rcp serves all 8 gate denominators, one serves both tanh(c); c kept packed.
__global__ __launch_bounds__(256)
void lstm_ac_kernel(const float* __restrict__ seq,
                    const int*   __restrict__ lengths,
                    const float* __restrict__ Wih0, const float* __restrict__ Whh0,
                    const float* __restrict__ bih0, const float* __restrict__ bhh0,
                    const float* __restrict__ Wih1, const float* __restrict__ Whh1,
                    const float* __restrict__ bih1, const float* __restrict__ bhh1,
                    const float* __restrict__ Wl,  const float* __restrict__ bl,
                    const float* __restrict__ Wv,  const float* __restrict__ bv,
                    const float* __restrict__ Wa,  const float* __restrict__ ba,
                    const float* __restrict__ log_std,
                    float* __restrict__ out)
{
    __shared__ __align__(16) float xstage[8][2][4][16][8]; // [warp][buf][grp][step][8] = 32 kB
    __shared__ __align__(16) float hbuf[8][4][2][8];       // [warp][grp][layer][m]

    const unsigned FULL = 0xffffffffu;
    int lane = threadIdx.x & 31;
    int wib  = threadIdx.x >> 5;            // 0..7
    int grp  = lane >> 3;                   // 0..3 (sequence within warp)
    int m    = lane & 7;                    // hidden unit owned by this lane

    // anti-correlated SMSP pairing (warps {k, k+4} share an SMSP)
    int gl = blockIdx.x + 128 * (wib & 3);
    int g  = (wib < 4) ? gl : (1023 - gl);

    int b   = g_perm[4 * g + grp];
    int len = lengths[b];
    int o1  = __shfl_xor_sync(FULL, len, 8);  int l2 = len > o1 ? len : o1;
    int o2  = __shfl_xor_sync(FULL, l2, 16);  int wmax = l2 > o2 ? l2 : o2;

    // activation prescale folded into weights/biases.
    const float SG = -1.4426950408889634f;
    const float TH = -2.8853900817779268f;
    const float scl[4] = {SG, SG, TH, SG};

    u64 w0x[4][4], w0h[4][4], w1x[4][4], w1h[4][4], bs0[4], bs1[4];
#pragma unroll
    for (int gi = 0; gi < 4; gi++) {
        int r = m + 8 * gi;
        float s = scl[gi];
#pragma unroll
        for (int j = 0; j < 4; j++) {
            w0x[gi][j] = pk2(Wih0[r*8+2*j]*s, Wih0[r*8+2*j+1]*s);
            w0h[gi][j] = pk2(Whh0[r*8+2*j]*s, Whh0[r*8+2*j+1]*s);
            w1x[gi][j] = pk2(Wih1[r*8+2*j]*s, Wih1[r*8+2*j+1]*s);
            w1h[gi][j] = pk2(Whh1[r*8+2*j]*s, Whh1[r*8+2*j+1]*s);
        }
        bs0[gi] = pk2((bih0[r] + bhh0[r]) * s, 0.f);
        bs1[gi] = pk2((bih1[r] + bhh1[r]) * s, 0.f);
    }

    // hoisted packed constants
    const u64 ONE2  = pk2(1.0f, 1.0f);
    const u64 TWO2  = pk2(2.0f, 2.0f);
    const u64 MONE2 = pk2(-1.0f, -1.0f);
    const u64 TH2   = pk2(TH, TH);

    const float* xrow = seq + (size_t)b * SS * INW;

    uint32_t st_base = (uint32_t)__cvta_generic_to_shared(&xstage[wib][0][grp][0][0]);
    uint32_t st_lane = st_base + (uint32_t)m * 64u;
    const uint32_t BUFSTRIDE = 4u * 16u * 8u * 4u;

    auto prefetch = [&](int cc) {
        int Tg = cc * 16 + 1 + 2 * m;
        if (Tg > SS - 2) Tg = SS - 2;
        const float* gsrc = xrow + (size_t)Tg * 8;
        uint32_t sdst = st_lane + (uint32_t)(cc & 1) * BUFSTRIDE;
        cpasync16(sdst,      gsrc);
        cpasync16(sdst + 16, gsrc + 4);
        cpasync16(sdst + 32, gsrc + 8);
        cpasync16(sdst + 48, gsrc + 12);
        cpcommit();
    };

    // ---- prologue: A(0) with h0(-1)=0 ----
    u64 cP;                                   // packed (c1, c0)
    u64 h1r[4] = {0, 0, 0, 0};
    u64 h0r[4];
    u64 yp[4]  = {0, 0, 0, 0};
    {
        ulonglong2 xa = ((const ulonglong2*)xrow)[0];
        ulonglong2 xb = ((const ulonglong2*)xrow)[1];
        u64 acc[4];
#pragma unroll
        for (int gi = 0; gi < 4; gi++) {
            u64 a = ffma2(w0x[gi][0], xa.x, bs0[gi]);
            a = ffma2(w0x[gi][1], xa.y, a);
            a = ffma2(w0x[gi][2], xb.x, a);
            a = ffma2(w0x[gi][3], xb.y, a);
            acc[gi] = a;
        }
        float iv = rcpf_(1.0f + ex2f_(hsum2(acc[0])));
        float gv = fmaf(2.0f, rcpf_(1.0f + ex2f_(hsum2(acc[2]))), -1.0f);
        float ov = rcpf_(1.0f + ex2f_(hsum2(acc[3])));
        float c0 = iv * gv;
        cP = pk2(0.f, c0);                    // (c1=0, c0)
        float h0m = ov * tanhf_(c0);
        hbuf[wib][grp][0][m] = h0m;
        __syncwarp();
        ulonglong2 q = *(const ulonglong2*)&hbuf[wib][grp][0][0];
        ulonglong2 p = *(const ulonglong2*)&hbuf[wib][grp][0][4];
        h0r[0] = q.x; h0r[1] = q.y; h0r[2] = p.x; h0r[3] = p.y;
    }

    int chunks = (wmax + 15) >> 4;
    prefetch(0);
    prefetch(1);

    // ---- main loop over chunks of 16 steps ----
    for (int c = 0; c < chunks; c++) {
        cpwait1();
        __syncwarp();
        const float* xbuf = &xstage[wib][c & 1][grp][0][0];
        int base_t = c << 4;
        int nst = wmax - base_t; if (nst > 16) nst = 16;

#pragma unroll 4
        for (int i = 0; i < nst; i++) {
            int t = base_t + i;

            const ulonglong2* xs = (const ulonglong2*)(xbuf + i * 8);
            ulonglong2 xa = xs[0], xb = xs[1];

            // ---- B(t): layer1 gates from h0r(t), h1r(t-1) ----
            u64 bcc[4];
#pragma unroll
            for (int gi = 0; gi < 4; gi++) {
                u64 p = ffma2(w1x[gi][0], h0r[0], bs1[gi]);
                p = ffma2(w1x[gi][1], h0r[1], p);
                p = ffma2(w1x[gi][2], h0r[2], p);
                p = ffma2(w1x[gi][3], h0r[3], p);
                u64 q = ffma2(w1h[gi][0], h1r[0], (u64)0);
                q = ffma2(w1h[gi][1], h1r[1], q);
                q = ffma2(w1h[gi][2], h1r[2], q);
                q = ffma2(w1h[gi][3], h1r[3], q);
                bcc[gi] = fadd2(p, q);
            }

            // ---- A(t+1): layer0 gates from x(t+1), h0r(t) ----
            u64 acc[4];
#pragma unroll
            for (int gi = 0; gi < 4; gi++) {
                u64 p = ffma2(w0h[gi][0], h0r[0], bs0[gi]);
                p = ffma2(w0h[gi][1], h0r[1], p);
                p = ffma2(w0h[gi][2], h0r[2], p);
                p = ffma2(w0h[gi][3], h0r[3], p);
                u64 q = ffma2(w0x[gi][0], xa.x, (u64)0);
                q = ffma2(w0x[gi][1], xa.y, q);
                q = ffma2(w0x[gi][2], xb.x, q);
                q = ffma2(w0x[gi][3], xb.y, q);
                acc[gi] = fadd2(p, q);
            }

            // ---- packed epilogue: lo = B(layer1), hi = A(layer0) ----
            // gate denominators d = 1 + 2^(arg), packed per gate index
            u64 D[4];
#pragma unroll
            for (int gi = 0; gi < 4; gi++) {
                float eB = ex2f_(hsum2(bcc[gi]));
                float eA = ex2f_(hsum2(acc[gi]));
                D[gi] = fadd2(pk2(eB, eA), ONE2);
            }
            // batched reciprocal over all 8 denominators
            u64 P01 = fmul2(D[0], D[1]);
            u64 P23 = fmul2(D[2], D[3]);
            u64 Pq  = fmul2(P01, P23);                   // (PB, PA)
            float PBs, PAs; unpk2(Pq, PBs, PAs);
            float R = rcpf_(PBs * PAs);
            u64 invPq = fmul2(pk2(R, R), pk2(PAs, PBs)); // (1/PB, 1/PA)
            u64 r01 = fmul2(invPq, P23);                 // 1/(d0*d1) pair
            u64 r23 = fmul2(invPq, P01);                 // 1/(d2*d3) pair
            // gates (packed): i=1/d0, f=1/d1, g=2/d2-1, o=1/d3
            u64 iP = fmul2(r01, D[1]);
            u64 fP = fmul2(r01, D[0]);
            u64 oP = fmul2(r23, D[2]);
            u64 gP = ffma2(TWO2, fmul2(r23, D[3]), MONE2);
            // packed c-update: (c1, c0) = f*(c1,c0) + i*g
            cP = ffma2(fP, cP, fmul2(iP, gP));
            // packed tanh(c): one rcp for both halves
            float tb, ta; unpk2(fmul2(cP, TH2), tb, ta);
            float etB = ex2f_(tb);
            float etA = ex2f_(ta);
            u64 tD = fadd2(pk2(etB, etA), ONE2);         // (tdB, tdA)
            float tdB, tdA; unpk2(tD, tdB, tdA);
            float tR = rcpf_(tdB * tdA);
            u64 tm = fmul2(pk2(tR, tR), pk2(tdA, tdB));  // (tR*tdA, tR*tdB)
            u64 hP = fmul2(oP, ffma2(TWO2, tm, MONE2));  // (h1m, h0m)
            float h1m, h0m; unpk2(hP, h1m, h0m);

            // single combined exchange point
            hbuf[wib][grp][0][m] = h0m;
            hbuf[wib][grp][1][m] = h1m;
            __syncwarp();
            ulonglong2 q0 = *(const ulonglong2*)&hbuf[wib][grp][0][0];
            ulonglong2 q1 = *(const ulonglong2*)&hbuf[wib][grp][0][4];
            ulonglong2 r0 = *(const ulonglong2*)&hbuf[wib][grp][1][0];
            ulonglong2 r1 = *(const ulonglong2*)&hbuf[wib][grp][1][4];
            h0r[0] = q0.x; h0r[1] = q0.y; h0r[2] = q1.x; h0r[3] = q1.y;
            h1r[0] = r0.x; h1r[1] = r0.y; h1r[2] = r1.x; h1r[3] = r1.y;

            if (t == len - 1) { yp[0] = h1r[0]; yp[1] = h1r[1]; yp[2] = h1r[2]; yp[3] = h1r[3]; }
        }

        prefetch(c + 2);
    }

    cpwaitall();
    __syncwarp();

    // ---- heads (lane m==0 of each group holds full y in yp) ----
    if (m == 0) {
        float y[8];
        unpk2(yp[0], y[0], y[1]);
        unpk2(yp[1], y[2], y[3]);
        unpk2(yp[2], y[4], y[5]);
        unpk2(yp[3], y[6], y[7]);

        float feat[4];
#pragma unroll
        for (int j = 0; j < 4; j++) {
            float a = bl[j];
#pragma unroll
            for (int k = 0; k < 8; k++) a = fmaf(Wl[j * 8 + k], y[k], a);
            feat[j] = tanhf_(a);
        }
        float val = bv[0];
#pragma unroll
        for (int j = 0; j < 4; j++) val = fmaf(Wv[j], feat[j], val);
        out[b] = val;
#pragma unroll
        for (int a = 0; a < 4; a++) {
            float mv = ba[a];
#pragma unroll
            for (int j = 0; j < 4; j++) mv = fmaf(Wa[a * 4 + j], feat[j], mv);
            float ls = log_std[a];
            out[BB + b * 4 + a]          = mv;                               // action_mean
            out[BB + 4 * BB + b * 4 + a] = ls;                               // action_log_std
            out[BB + 8 * BB + b * 4 + a] = ex2f_(ls * 1.4426950408889634f);  // action_std
        }
    }
}

extern "C" void kernel_launch(void* const* d_in, const int* in_sizes, int n_in,
                              void* d_out, int out_size)
{
    const float* seq     = (const float*)d_in[0];
    const int*   lengths = (const int*)  d_in[1];
    const float* Wih0 = (const float*)d_in[2];
    const float* Whh0 = (const float*)d_in[3];
    const float* bih0 = (const float*)d_in[4];
    const float* bhh0 = (const float*)d_in[5];
    const float* Wih1 = (const float*)d_in[6];
    const float* Whh1 = (const float*)d_in[7];
    const float* bih1 = (const float*)d_in[8];
    const float* bhh1 = (const float*)d_in[9];
    const float* Wl   = (const float*)d_in[10];
    const float* bl   = (const float*)d_in[11];
    const float* Wv   = (const float*)d_in[12];
    const float* bv   = (const float*)d_in[13];
    const float* Wa   = (const float*)d_in[14];
    const float* ba   = (const float*)d_in[15];
    const float* log_std = (const float*)d_in[16];
    float* out = (float*)d_out;

    // length-descending counting sort -> g_perm
    k_zero<<<(SS + 1023) / 1024, 1024>>>();
    k_hist<<<(BB + 255) / 256, 256>>>(lengths);
    k_scan<<<1, 1024>>>();
    k_scatter<<<(BB + 255) / 256, 256>>>(lengths);

    // main: 1024 warps (4 seqs each, 8 lanes/seq), 128 blocks x 256 threads = ONE wave
    lstm_ac_kernel<<<128, 256>>>(seq, lengths,
                                 Wih0, Whh0, bih0, bhh0,
                                 Wih1, Whh1, bih1, bhh1,
                                 Wl, bl, Wv, bv, Wa, ba, log_std,
                                 out);
}

// round 12
// speedup vs baseline: 2.0737x; 1.0688x over previous
#include <cuda_runtime.h>
#include <cstdint>

// Problem constants (fixed shapes)
#define BB 4096
#define SS 2048
#define INW 8
#define HH 8

typedef unsigned long long u64;

__device__ int g_perm[BB];

// ---------------- scalar helpers --------------
__device__ __forceinline__ float ex2f_(float x) {
    float r; asm("ex2.approx.f32 %0, %1;" : "=f"(r) : "f"(x)); return r;
}
__device__ __forceinline__ float rcpf_(float x) {
    float r; asm("rcp.approx.f32 %0, %1;" : "=f"(r) : "f"(x)); return r;
}
__device__ __forceinline__ float tanhf_(float x) {
    return fmaf(2.0f, rcpf_(1.0f + ex2f_(-2.8853900817779268f * x)), -1.0f);
}

// ---------------- packed f32x2 helpers (sm_103a) --------------
__device__ __forceinline__ u64 pk2(float lo, float hi) {
    u64 r; asm("mov.b64 %0, {%1, %2};" : "=l"(r) : "f"(lo), "f"(hi)); return r;
}
__device__ __forceinline__ void unpk2(u64 v, float& lo, float& hi) {
    asm("mov.b64 {%0, %1}, %2;" : "=f"(lo), "=f"(hi) : "l"(v));
}
__device__ __forceinline__ u64 ffma2(u64 a, u64 b, u64 c) {
    u64 d; asm("fma.rn.f32x2 %0, %1, %2, %3;" : "=l"(d) : "l"(a), "l"(b), "l"(c)); return d;
}
__device__ __forceinline__ u64 fadd2(u64 a, u64 b) {
    u64 d; asm("add.rn.f32x2 %0, %1, %2;" : "=l"(d) : "l"(a), "l"(b)); return d;
}
__device__ __forceinline__ float hsum2(u64 v) {
    float lo, hi; unpk2(v, lo, hi); return lo + hi;
}

// ---------------- smem ld/st helpers (explicit shared space) --------------
__device__ __forceinline__ void lds2u64(uint32_t a, u64& x, u64& y) {
    asm volatile("ld.shared.v2.u64 {%0, %1}, [%2];" : "=l"(x), "=l"(y) : "r"(a));
}
__device__ __forceinline__ void sts_f32(uint32_t a, float v) {
    asm volatile("st.shared.f32 [%0], %1;" :: "r"(a), "f"(v));
}

// ---------------- cp.async helpers --------------
__device__ __forceinline__ void cpasync16(uint32_t saddr, const void* gaddr) {
    asm volatile("cp.async.cg.shared.global [%0], [%1], 16;\n" :: "r"(saddr), "l"(gaddr));
}
__device__ __forceinline__ void cpcommit() {
    asm volatile("cp.async.commit_group;\n" ::: "memory");
}
__device__ __forceinline__ void cpwait1() {
    asm volatile("cp.async.wait_group 1;\n" ::: "memory");
}
__device__ __forceinline__ void cpwaitall() {
    asm volatile("cp.async.wait_all;\n" ::: "memory");
}

// ---------------- fused counting sort (one block): hist + scan + scatter ----------------
__global__ __launch_bounds__(1024)
void k_sort(const int* __restrict__ lengths)
{
    __shared__ int sa[SS];
    __shared__ int sb[SS];
    int t = threadIdx.x;
    sa[t] = 0; sa[t + 1024] = 0;
    __syncthreads();
    for (int b = t; b < BB; b += 1024)
        atomicAdd(&sa[SS - lengths[b]], 1);
    __syncthreads();
    int* src = sa; int* dst = sb;
    for (int off = 1; off < SS; off <<= 1) {
        for (int i = t; i < SS; i += 1024) {
            int v = src[i];
            if (i >= off) v += src[i - off];
            dst[i] = v;
        }
        __syncthreads();
        int* tmp = src; src = dst; dst = tmp;
    }
    // exclusive offsets into the free buffer
    for (int i = t; i < SS; i += 1024)
        dst[i] = (i == 0) ? 0 : src[i - 1];
    __syncthreads();
    for (int b = t; b < BB; b += 1024) {
        int key = SS - lengths[b];
        int p = atomicAdd(&dst[key], 1);
        g_perm[p] = b;
    }
}

// ---------------- main LSTM kernel ----------------
// Layer-split lanes: 16 lanes/seq (8 per layer), 2 seqs/warp, 2048 warps =
// 128 blocks x 512 threads (1 block/SM, 4 warps/SMSP -> stall hiding).
// Lane (grp, L, m): owns hidden unit m of layer L of sequence grp. Both layers
// run the SAME instruction stream; only pointers differ:
//   layer0: in1 = staged x(t+1) (smem), in2 = h0(t)    [A(t+1) pipeline stage]
//   layer1: in1 = h0(t),               in2 = h1(t-1)   [B(t)   pipeline stage]
// One smem h-exchange + __syncwarp per step. x staged via cp.async
// (8-step chunks, double buffer, 2 ahead).
// SMSP balance: warps {k,k+4,k+8,k+12} get groups {u,1023-u,1024+u,2047-u}
// -> per-SMSP total steps ~const (~4098).
__global__ __launch_bounds__(512)
void lstm_ac_kernel(const float* __restrict__ seq,
                    const int*   __restrict__ lengths,
                    const float* __restrict__ Wih0, const float* __restrict__ Whh0,
                    const float* __restrict__ bih0, const float* __restrict__ bhh0,
                    const float* __restrict__ Wih1, const float* __restrict__ Whh1,
                    const float* __restrict__ bih1, const float* __restrict__ bhh1,
                    const float* __restrict__ Wl,  const float* __restrict__ bl,
                    const float* __restrict__ Wv,  const float* __restrict__ bv,
                    const float* __restrict__ Wa,  const float* __restrict__ ba,
                    const float* __restrict__ log_std,
                    float* __restrict__ out)
{
    __shared__ __align__(16) float xstage[16][2][2][8][8]; // [warp][buf][grp][step][8] = 32 kB
    __shared__ __align__(16) float hbuf[16][2][2][8];      // [warp][grp][layer][m]
    __shared__ __align__(16) float ybuf[16][2][8];         // final h1 snapshot

    const unsigned FULL = 0xffffffffu;
    int lane = threadIdx.x & 31;
    int wib  = threadIdx.x >> 5;       // 0..15
    int grp  = lane >> 4;              // 0..1 (sequence within warp)
    int L    = (lane >> 3) & 1;        // layer owned by this lane
    int m    = lane & 7;               // hidden unit owned by this lane

    // SMSP-balanced group assignment
    int smsp = wib & 3;
    int k    = wib >> 2;               // 0..3 (warp slot on its SMSP)
    int u    = blockIdx.x * 4 + smsp;  // 0..511
    int p = u;
    if (k == 1) p = 1023 - u;
    else if (k == 2) p = 1024 + u;
    else if (k == 3) p = 2047 - u;

    int b   = g_perm[2 * p + grp];
    int len = lengths[b];
    int ol  = __shfl_xor_sync(FULL, len, 16);
    int wmax = len > ol ? len : ol;

    // activation prescale folded into weights/biases (gate order i,f,g,o)
    const float SG = -1.4426950408889634f;
    const float TH = -2.8853900817779268f;
    const float scl[4] = {SG, SG, TH, SG};

    const float* Wi = L ? Wih1 : Wih0;   // in1 matrix
    const float* Wh = L ? Whh1 : Whh0;   // in2 matrix
    const float* Bi = L ? bih1 : bih0;
    const float* Bh = L ? bhh1 : bhh0;

    u64 w1[4][4], w2[4][4];
    float bs[4];
#pragma unroll
    for (int gi = 0; gi < 4; gi++) {
        int r = m + 8 * gi;
        float s = scl[gi];
#pragma unroll
        for (int j = 0; j < 4; j++) {
            w1[gi][j] = pk2(Wi[r*8+2*j]*s, Wi[r*8+2*j+1]*s);
            w2[gi][j] = pk2(Wh[r*8+2*j]*s, Wh[r*8+2*j+1]*s);
        }
        bs[gi] = (Bi[r] + Bh[r]) * s;
    }

    const float* xrow = seq + (size_t)b * SS * INW;

    // smem addresses
    uint32_t a_xbase = (uint32_t)__cvta_generic_to_shared(&xstage[wib][0][grp][0][0]);
    uint32_t a_h0    = (uint32_t)__cvta_generic_to_shared(&hbuf[wib][grp][0][0]);
    uint32_t a_in2   = (uint32_t)__cvta_generic_to_shared(&hbuf[wib][grp][L][0]);
    uint32_t a_hm    = a_in2 + (uint32_t)m * 4u;          // own h write slot
    const uint32_t BUFST = 2u * 8u * 8u * 4u;             // 512 B between buffers

    // prefetch chunk cc: stages x[cc*8+1 .. cc*8+8]; lane (grp, q=lane&15) loads 16B
    int q = lane & 15;
    auto prefetch = [&](int cc) {
        int Tg = cc * 8 + 1 + (q >> 1);
        if (Tg > SS - 1) Tg = SS - 1;     // clamp (feeds only discarded A steps)
        const float* gsrc = xrow + (size_t)Tg * 8 + (q & 1) * 4;
        cpasync16(a_xbase + (uint32_t)(cc & 1) * BUFST + (uint32_t)q * 16u, gsrc);
        cpcommit();
    };

    // ---- prologue: layer0 lanes compute h0(0) from x(0), h=0; layer1 lanes -> 0 ----
    float c;
    {
        ulonglong2 xa = ((const ulonglong2*)xrow)[0];
        ulonglong2 xb = ((const ulonglong2*)xrow)[1];
        float d[4];
#pragma unroll
        for (int gi = 0; gi < 4; gi++) {
            u64 a = ffma2(w1[gi][0], xa.x, pk2(bs[gi], 0.f));
            a = ffma2(w1[gi][1], xa.y, a);
            a = ffma2(w1[gi][2], xb.x, a);
            a = ffma2(w1[gi][3], xb.y, a);
            d[gi] = 1.0f + ex2f_(hsum2(a));
        }
        float p01 = d[0]*d[1], p23 = d[2]*d[3];
        float R = rcpf_(p01 * p23);
        float r01 = R * p23, r23 = R * p01;
        float iv = r01 * d[1];
        float gv = fmaf(2.0f, r23 * d[3], -1.0f);
        float ov = r23 * d[2];
        float c0 = iv * gv;
        float h0m = ov * tanhf_(c0);
        c = L ? 0.f : c0;
        sts_f32(a_hm, L ? 0.f : h0m);
        __syncwarp();
    }

    int chunks = (wmax + 7) >> 3;
    prefetch(0);
    prefetch(1);

    float ym = 0.f;   // layer1 lanes: snapshot of h1_m at t == len-1

    // ---- main loop over chunks of 8 steps ----
    for (int cc = 0; cc < chunks; cc++) {
        cpwait1();
        __syncwarp();
        uint32_t a_xc = a_xbase + (uint32_t)(cc & 1) * BUFST;
        int base_t = cc << 3;
        int nst = wmax - base_t; if (nst > 8) nst = 8;

#pragma unroll 4
        for (int i = 0; i < nst; i++) {
            int t = base_t + i;

            // in1: layer0 -> staged x(t+1); layer1 -> h0(t). in2: own-layer h.
            uint32_t a_in1 = L ? a_h0 : (a_xc + (uint32_t)i * 32u);
            u64 i1a, i1b, i1c, i1d, i2a, i2b, i2c, i2d;
            lds2u64(a_in1,       i1a, i1b);
            lds2u64(a_in1 + 16u, i1c, i1d);
            lds2u64(a_in2,       i2a, i2b);
            lds2u64(a_in2 + 16u, i2c, i2d);

            // 4 gates: two parallel ffma2 chains + fadd2 each
            float d[4];
#pragma unroll
            for (int gi = 0; gi < 4; gi++) {
                u64 pa = ffma2(w1[gi][0], i1a, pk2(bs[gi], 0.f));
                pa = ffma2(w1[gi][1], i1b, pa);
                pa = ffma2(w1[gi][2], i1c, pa);
                pa = ffma2(w1[gi][3], i1d, pa);
                u64 pb = ffma2(w2[gi][0], i2a, (u64)0);
                pb = ffma2(w2[gi][1], i2b, pb);
                pb = ffma2(w2[gi][2], i2c, pb);
                pb = ffma2(w2[gi][3], i2d, pb);
                d[gi] = 1.0f + ex2f_(hsum2(fadd2(pa, pb)));
            }

            // batched reciprocal over the 4 gate denominators
            float p01 = d[0]*d[1], p23 = d[2]*d[3];
            float R = rcpf_(p01 * p23);
            float r01 = R * p23, r23 = R * p01;
            float iv = r01 * d[1];
            float fv = r01 * d[0];
            float gv = fmaf(2.0f, r23 * d[3], -1.0f);
            float ov = r23 * d[2];
            c = fmaf(fv, c, iv * gv);

            // tanh(c), h
            float e = ex2f_(c * TH);
            float tr = rcpf_(1.0f + e);
            float h = ov * fmaf(2.0f, tr, -1.0f);

            // layer1 lanes snapshot final h1_m
            ym = ((t == len - 1) & L) ? h : ym;

            // exchange
            sts_f32(a_hm, h);
            __syncwarp();
        }

        prefetch(cc + 2);
    }

    // publish y (layer1 lanes) then heads
    if (L) ybuf[wib][grp][m] = ym;
    cpwaitall();
    __syncwarp();

    if ((lane & 15) == 0) {
        float y[8];
#pragma unroll
        for (int j = 0; j < 8; j++) y[j] = ybuf[wib][grp][j];

        float feat[4];
#pragma unroll
        for (int j = 0; j < 4; j++) {
            float a = bl[j];
#pragma unroll
            for (int kk = 0; kk < 8; kk++) a = fmaf(Wl[j * 8 + kk], y[kk], a);
            feat[j] = tanhf_(a);
        }
        float val = bv[0];
#pragma unroll
        for (int j = 0; j < 4; j++) val = fmaf(Wv[j], feat[j], val);
        out[b] = val;
#pragma unroll
        for (int a = 0; a < 4; a++) {
            float mv = ba[a];
#pragma unroll
            for (int j = 0; j < 4; j++) mv = fmaf(Wa[a * 4 + j], feat[j], mv);
            float ls = log_std[a];
            out[BB + b * 4 + a]          = mv;                               // action_mean
            out[BB + 4 * BB + b * 4 + a] = ls;                               // action_log_std
            out[BB + 8 * BB + b * 4 + a] = ex2f_(ls * 1.4426950408889634f);  // action_std
        }
    }
}

extern "C" void kernel_launch(void* const* d_in, const int* in_sizes, int n_in,
                              void* d_out, int out_size)
{
    const float* seq     = (const float*)d_in[0];
    const int*   lengths = (const int*)  d_in[1];
    const float* Wih0 = (const float*)d_in[2];
    const float* Whh0 = (const float*)d_in[3];
    const float* bih0 = (const float*)d_in[4];
    const float* bhh0 = (const float*)d_in[5];
    const float* Wih1 = (const float*)d_in[6];
    const float* Whh1 = (const float*)d_in[7];
    const float* bih1 = (const float*)d_in[8];
    const float* bhh1 = (const float*)d_in[9];
    const float* Wl   = (const float*)d_in[10];
    const float* bl   = (const float*)d_in[11];
    const float* Wv   = (const float*)d_in[12];
    const float* bv   = (const float*)d_in[13];
    const float* Wa   = (const float*)d_in[14];
    const float* ba   = (const float*)d_in[15];
    const float* log_std = (const float*)d_in[16];
    float* out = (float*)d_out;

    // fused length-descending counting sort -> g_perm (one launch)
    k_sort<<<1, 1024>>>(lengths);

    // main: 2048 warps (2 seqs each, 16 lanes/seq, layer-split),
    // 128 blocks x 512 threads = 1 block/SM, 4 warps/SMSP
    lstm_ac_kernel<<<128, 512>>>(seq, lengths,
                                 Wih0, Whh0, bih0, bhh0,
                                 Wih1, Whh1, bih1, bhh1,
                                 Wl, bl, Wv, bv, Wa, ba, log_std,
                                 out);
}

// round 14
// speedup vs baseline: 2.1420x; 1.0329x over previous
#include <cuda_runtime.h>
#include <cstdint>

// Problem constants (fixed shapes)
#define BB 4096
#define SS 2048
#define INW 8
#define HH 8

typedef unsigned long long u64;

__device__ int g_perm[BB];

// ---------------- scalar helpers --------------
__device__ __forceinline__ float ex2f_(float x) {
    float r; asm("ex2.approx.f32 %0, %1;" : "=f"(r) : "f"(x)); return r;
}
__device__ __forceinline__ float rcpf_(float x) {
    float r; asm("rcp.approx.f32 %0, %1;" : "=f"(r) : "f"(x)); return r;
}
__device__ __forceinline__ float tanhf_(float x) {
    return fmaf(2.0f, rcpf_(1.0f + ex2f_(-2.8853900817779268f * x)), -1.0f);
}

// ---------------- packed f32x2 helpers (sm_103a) --------------
__device__ __forceinline__ u64 pk2(float lo, float hi) {
    u64 r; asm("mov.b64 %0, {%1, %2};" : "=l"(r) : "f"(lo), "f"(hi)); return r;
}
__device__ __forceinline__ void unpk2(u64 v, float& lo, float& hi) {
    asm("mov.b64 {%0, %1}, %2;" : "=f"(lo), "=f"(hi) : "l"(v));
}
__device__ __forceinline__ u64 ffma2(u64 a, u64 b, u64 c) {
    u64 d; asm("fma.rn.f32x2 %0, %1, %2, %3;" : "=l"(d) : "l"(a), "l"(b), "l"(c)); return d;
}
__device__ __forceinline__ u64 fadd2(u64 a, u64 b) {
    u64 d; asm("add.rn.f32x2 %0, %1, %2;" : "=l"(d) : "l"(a), "l"(b)); return d;
}
__device__ __forceinline__ float hsum2(u64 v) {
    float lo, hi; unpk2(v, lo, hi); return lo + hi;
}

// ---------------- smem ld/st helpers (explicit shared space) --------------
__device__ __forceinline__ void lds2u64(uint32_t a, u64& x, u64& y) {
    asm volatile("ld.shared.v2.u64 {%0, %1}, [%2];" : "=l"(x), "=l"(y) : "r"(a));
}
__device__ __forceinline__ void sts_f32(uint32_t a, float v) {
    asm volatile("st.shared.f32 [%0], %1;" :: "r"(a), "f"(v));
}

// ---------------- cp.async helpers --------------
__device__ __forceinline__ void cpasync16(uint32_t saddr, const void* gaddr) {
    asm volatile("cp.async.cg.shared.global [%0], [%1], 16;\n" :: "r"(saddr), "l"(gaddr));
}
__device__ __forceinline__ void cpcommit() {
    asm volatile("cp.async.commit_group;\n" ::: "memory");
}
__device__ __forceinline__ void cpwait1() {
    asm volatile("cp.async.wait_group 1;\n" ::: "memory");
}
__device__ __forceinline__ void cpwaitall() {
    asm volatile("cp.async.wait_all;\n" ::: "memory");
}

// ---------------- fused counting sort (one block): hist + scan + scatter ----------------
__global__ __launch_bounds__(1024)
void k_sort(const int* __restrict__ lengths)
{
    __shared__ int sa[SS];
    __shared__ int sb[SS];
    int t = threadIdx.x;
    sa[t] = 0; sa[t + 1024] = 0;
    __syncthreads();
    for (int b = t; b < BB; b += 1024)
        atomicAdd(&sa[SS - lengths[b]], 1);
    __syncthreads();
    int* src = sa; int* dst = sb;
    for (int off = 1; off < SS; off <<= 1) {
        for (int i = t; i < SS; i += 1024) {
            int v = src[i];
            if (i >= off) v += src[i - off];
            dst[i] = v;
        }
        __syncthreads();
        int* tmp = src; src = dst; dst = tmp;
    }
    // exclusive offsets into the free buffer
    for (int i = t; i < SS; i += 1024)
        dst[i] = (i == 0) ? 0 : src[i - 1];
    __syncthreads();
    for (int b = t; b < BB; b += 1024) {
        int key = SS - lengths[b];
        int p = atomicAdd(&dst[key], 1);
        g_perm[p] = b;
    }
}

// ---------------- main LSTM kernel ----------------
// Layer-split lanes: 16 lanes/seq (8 per layer), 2 seqs/warp.
// 148 blocks x 512 threads = 592 SMSPs, up to 4 warps each; 2048 groups snake-
// assigned over (SMSP s, slot k): k0->s, k1->1183-s, k2->1184+s, k3->2367-s
// (k3 invalid for s<320 -> warp exits; lands on SMSPs holding longest groups).
// Both layers run the SAME instruction stream; only pointers differ:
//   layer0: in1 = staged x(t+1) (smem), in2 = h0(t)
//   layer1: in1 = h0(t),               in2 = h1(t-1)
// Inner loop is fully convergent; smem exchange relies on the in-order shared
// pipe of a converged warp (all smem ops asm volatile) -> NO per-step barrier.
__global__ __launch_bounds__(512)
void lstm_ac_kernel(const float* __restrict__ seq,
                    const int*   __restrict__ lengths,
                    const float* __restrict__ Wih0, const float* __restrict__ Whh0,
                    const float* __restrict__ bih0, const float* __restrict__ bhh0,
                    const float* __restrict__ Wih1, const float* __restrict__ Whh1,
                    const float* __restrict__ bih1, const float* __restrict__ bhh1,
                    const float* __restrict__ Wl,  const float* __restrict__ bl,
                    const float* __restrict__ Wv,  const float* __restrict__ bv,
                    const float* __restrict__ Wa,  const float* __restrict__ ba,
                    const float* __restrict__ log_std,
                    float* __restrict__ out)
{
    __shared__ __align__(16) float xstage[16][2][2][8][8]; // [warp][buf][grp][step][8] = 32 kB
    __shared__ __align__(16) float hbuf[16][2][2][8];      // [warp][grp][layer][m]
    __shared__ __align__(16) float ybuf[16][2][8];         // final h1 snapshot

    const unsigned FULL = 0xffffffffu;
    int lane = threadIdx.x & 31;
    int wib  = threadIdx.x >> 5;       // 0..15
    int grp  = lane >> 4;              // 0..1 (sequence within warp)
    int L    = (lane >> 3) & 1;        // layer owned by this lane
    int m    = lane & 7;               // hidden unit owned by this lane

    // snake group assignment over 592 SMSPs x 4 slots
    int smsp = wib & 3;
    int k    = wib >> 2;               // 0..3 (warp slot on its SMSP)
    int s    = blockIdx.x * 4 + smsp;  // global SMSP id, 0..591
    int p;
    if      (k == 0) p = s;
    else if (k == 1) p = 1183 - s;
    else if (k == 2) p = 1184 + s;
    else             p = 2367 - s;
    if (p >= BB / 2) return;           // idle slot (k==3, s<320) — warp-uniform exit

    int b   = g_perm[2 * p + grp];
    int len = lengths[b];
    int ol  = __shfl_xor_sync(FULL, len, 16);
    int wmax = len > ol ? len : ol;

    // activation prescale folded into weights/biases (gate order i,f,g,o)
    const float SG = -1.4426950408889634f;
    const float TH = -2.8853900817779268f;
    const float scl[4] = {SG, SG, TH, SG};

    const float* Wi = L ? Wih1 : Wih0;   // in1 matrix
    const float* Wh = L ? Whh1 : Whh0;   // in2 matrix
    const float* Bi = L ? bih1 : bih0;
    const float* Bh = L ? bhh1 : bhh0;

    u64 w1[4][4], w2[4][4];
    float bs[4];
#pragma unroll
    for (int gi = 0; gi < 4; gi++) {
        int r = m + 8 * gi;
        float sc = scl[gi];
#pragma unroll
        for (int j = 0; j < 4; j++) {
            w1[gi][j] = pk2(Wi[r*8+2*j]*sc, Wi[r*8+2*j+1]*sc);
            w2[gi][j] = pk2(Wh[r*8+2*j]*sc, Wh[r*8+2*j+1]*sc);
        }
        bs[gi] = (Bi[r] + Bh[r]) * sc;
    }

    const float* xrow = seq + (size_t)b * SS * INW;

    // smem addresses
    uint32_t a_xbase = (uint32_t)__cvta_generic_to_shared(&xstage[wib][0][grp][0][0]);
    uint32_t a_h0    = (uint32_t)__cvta_generic_to_shared(&hbuf[wib][grp][0][0]);
    uint32_t a_in2   = (uint32_t)__cvta_generic_to_shared(&hbuf[wib][grp][L][0]);
    uint32_t a_hm    = a_in2 + (uint32_t)m * 4u;          // own h write slot
    const uint32_t BUFST = 2u * 8u * 8u * 4u;             // 512 B between buffers

    // prefetch chunk cc: stages x[cc*8+1 .. cc*8+8]; lane (grp, q=lane&15) loads 16B
    int q = lane & 15;
    auto prefetch = [&](int cc) {
        int Tg = cc * 8 + 1 + (q >> 1);
        if (Tg > SS - 1) Tg = SS - 1;     // clamp (feeds only discarded A steps)
        const float* gsrc = xrow + (size_t)Tg * 8 + (q & 1) * 4;
        cpasync16(a_xbase + (uint32_t)(cc & 1) * BUFST + (uint32_t)q * 16u, gsrc);
        cpcommit();
    };

    // ---- prologue: layer0 lanes compute h0(0) from x(0), h=0; layer1 lanes -> 0 ----
    float c;
    {
        ulonglong2 xa = ((const ulonglong2*)xrow)[0];
        ulonglong2 xb = ((const ulonglong2*)xrow)[1];
        float d[4];
#pragma unroll
        for (int gi = 0; gi < 4; gi++) {
            u64 a = ffma2(w1[gi][0], xa.x, pk2(bs[gi], 0.f));
            a = ffma2(w1[gi][1], xa.y, a);
            a = ffma2(w1[gi][2], xb.x, a);
            a = ffma2(w1[gi][3], xb.y, a);
            d[gi] = 1.0f + ex2f_(hsum2(a));
        }
        float p01 = d[0]*d[1], p23 = d[2]*d[3];
        float R = rcpf_(p01 * p23);
        float r01 = R * p23, r23 = R * p01;
        float iv = r01 * d[1];
        float gv = fmaf(2.0f, r23 * d[3], -1.0f);
        float ov = r23 * d[2];
        float c0 = iv * gv;
        float h0m = ov * tanhf_(c0);
        c = L ? 0.f : c0;
        sts_f32(a_hm, L ? 0.f : h0m);
        __syncwarp();
    }

    int chunks = (wmax + 7) >> 3;
    prefetch(0);
    prefetch(1);

    float ym = 0.f;   // layer1 lanes: snapshot of h1_m at t == len-1

    // ---- main loop over chunks of 8 steps ----
    for (int cc = 0; cc < chunks; cc++) {
        cpwait1();
        __syncwarp();
        uint32_t a_xc = a_xbase + (uint32_t)(cc & 1) * BUFST;
        int base_t = cc << 3;
        int nst = wmax - base_t; if (nst > 8) nst = 8;

#pragma unroll 4
        for (int i = 0; i < nst; i++) {
            int t = base_t + i;

            // in1: layer0 -> staged x(t+1); layer1 -> h0(t). in2: own-layer h.
            uint32_t a_in1 = L ? a_h0 : (a_xc + (uint32_t)i * 32u);
            u64 i1a, i1b, i1c, i1d, i2a, i2b, i2c, i2d;
            lds2u64(a_in1,       i1a, i1b);
            lds2u64(a_in1 + 16u, i1c, i1d);
            lds2u64(a_in2,       i2a, i2b);
            lds2u64(a_in2 + 16u, i2c, i2d);

            // 4 gates: two parallel ffma2 chains + fadd2 each
            float d[4];
#pragma unroll
            for (int gi = 0; gi < 4; gi++) {
                u64 pa = ffma2(w1[gi][0], i1a, pk2(bs[gi], 0.f));
                pa = ffma2(w1[gi][1], i1b, pa);
                pa = ffma2(w1[gi][2], i1c, pa);
                pa = ffma2(w1[gi][3], i1d, pa);
                u64 pb = ffma2(w2[gi][0], i2a, (u64)0);
                pb = ffma2(w2[gi][1], i2b, pb);
                pb = ffma2(w2[gi][2], i2c, pb);
                pb = ffma2(w2[gi][3], i2d, pb);
                d[gi] = 1.0f + ex2f_(hsum2(fadd2(pa, pb)));
            }

            // batched reciprocal over the 4 gate denominators
            float p01 = d[0]*d[1], p23 = d[2]*d[3];
            float R = rcpf_(p01 * p23);
            float r01 = R * p23, r23 = R * p01;
            float iv = r01 * d[1];
            float fv = r01 * d[0];
            float gv = fmaf(2.0f, r23 * d[3], -1.0f);
            float ov = r23 * d[2];
            c = fmaf(fv, c, iv * gv);

            // tanh(c), h
            float e = ex2f_(c * TH);
            float tr = rcpf_(1.0f + e);
            float h = ov * fmaf(2.0f, tr, -1.0f);

            // layer1 lanes snapshot final h1_m (SEL, no branch)
            ym = ((t == len - 1) & L) ? h : ym;

            // exchange: converged warp, in-order shared pipe — no barrier needed
            sts_f32(a_hm, h);
        }

        prefetch(cc + 2);
    }

    // publish y (layer1 lanes) then heads
    if (L) ybuf[wib][grp][m] = ym;
    cpwaitall();
    __syncwarp();

    if ((lane & 15) == 0) {
        float y[8];
#pragma unroll
        for (int j = 0; j < 8; j++) y[j] = ybuf[wib][grp][j];

        float feat[4];
#pragma unroll
        for (int j = 0; j < 4; j++) {
            float a = bl[j];
#pragma unroll
            for (int kk = 0; kk < 8; kk++) a = fmaf(Wl[j * 8 + kk], y[kk], a);
            feat[j] = tanhf_(a);
        }
        float val = bv[0];
#pragma unroll
        for (int j = 0; j < 4; j++) val = fmaf(Wv[j], feat[j], val);
        out[b] = val;
#pragma unroll
        for (int a = 0; a < 4; a++) {
            float mv = ba[a];
#pragma unroll
            for (int j = 0; j < 4; j++) mv = fmaf(Wa[a * 4 + j], feat[j], mv);
            float ls = log_std[a];
            out[BB + b * 4 + a]          = mv;                               // action_mean
            out[BB + 4 * BB + b * 4 + a] = ls;                               // action_log_std
            out[BB + 8 * BB + b * 4 + a] = ex2f_(ls * 1.4426950408889634f);  // action_std
        }
    }
}

extern "C" void kernel_launch(void* const* d_in, const int* in_sizes, int n_in,
                              void* d_out, int out_size)
{
    const float* seq     = (const float*)d_in[0];
    const int*   lengths = (const int*)  d_in[1];
    const float* Wih0 = (const float*)d_in[2];
    const float* Whh0 = (const float*)d_in[3];
    const float* bih0 = (const float*)d_in[4];
    const float* bhh0 = (const float*)d_in[5];
    const float* Wih1 = (const float*)d_in[6];
    const float* Whh1 = (const float*)d_in[7];
    const float* bih1 = (const float*)d_in[8];
    const float* bhh1 = (const float*)d_in[9];
    const float* Wl   = (const float*)d_in[10];
    const float* bl   = (const float*)d_in[11];
    const float* Wv   = (const float*)d_in[12];
    const float* bv   = (const float*)d_in[13];
    const float* Wa   = (const float*)d_in[14];
    const float* ba   = (const float*)d_in[15];
    const float* log_std = (const float*)d_in[16];
    float* out = (float*)d_out;

    // fused length-descending counting sort -> g_perm (one launch)
    k_sort<<<1, 1024>>>(lengths);

    // main: 148 blocks x 512 threads -> 592 SMSPs, snake-balanced 2048 groups
    lstm_ac_kernel<<<148, 512>>>(seq, lengths,
                                 Wih0, Whh0, bih0, bhh0,
                                 Wih1, Whh1, bih1, bhh1,
                                 Wl, bl, Wv, bv, Wa, ba, log_std,
                                 out);
}